// round 2
// baseline (speedup 1.0000x reference)
#include <cuda_runtime.h>
#include <math.h>

// R1 resubmit: R0 source unchanged (R0 bench was a broker infra failure).

// ---------------- problem constants ----------------
#define BB   8
#define MM   1024
#define DD   768
#define NE   32
#define PE   32
#define KK   8
#define HH   2048
#define SS   1024            // N*P
#define TT   8192            // B*M

// ---------------- scratch (device globals; no allocs allowed) ----------------
__device__ float g_xn   [TT * DD];          // xn, then xw in-place
__device__ float g_phin [DD * SS];
__device__ float g_part [32 * NE * DD];     // 32 token-groups x [N, D] partials
__device__ float g_cpart[32 * NE];          // per-token-group counts
__device__ float g_mean [NE * DD];
__device__ float g_mad  [NE * DD];          // w_mad (already divided by count)
__device__ float g_W    [NE * DD];
__device__ float g_cnt  [NE];
__device__ float g_logits[TT * SS];         // logits, later overwritten by comb
__device__ float g_disp [TT * SS];
__device__ float g_rowmax[TT], g_rowsum[TT];
__device__ float g_colmax[BB * SS], g_colsum[BB * SS];
__device__ float g_xs [NE * (BB*PE) * DD];  // [n][b*32+p][d]
__device__ float g_h  [NE * (BB*PE) * HH];
__device__ float g_ys [NE * (BB*PE) * DD];

__device__ __forceinline__ float gelu_f(float v) {
    return 0.5f * v * (1.0f + erff(v * 0.70710678118654752440f));
}

// ---------------- token L2 normalize ----------------
__global__ void k_norm_x(const float* __restrict__ x) {
    int t = blockIdx.x, tid = threadIdx.x;
    const float* xr = x + (size_t)t * DD;
    float v0 = xr[tid], v1 = xr[tid + 256], v2 = xr[tid + 512];
    __shared__ float red[256];
    red[tid] = v0*v0 + v1*v1 + v2*v2;
    __syncthreads();
    for (int o = 128; o; o >>= 1) { if (tid < o) red[tid] += red[tid+o]; __syncthreads(); }
    float inv = 1.0f / fmaxf(sqrtf(red[0]), 1e-12f);
    float* o = g_xn + (size_t)t * DD;
    o[tid] = v0*inv; o[tid+256] = v1*inv; o[tid+512] = v2*inv;
}

// ---------------- phi column normalize + scale ----------------
__global__ void k_norm_phi(const float* __restrict__ phi, const float* __restrict__ scale) {
    int c = blockIdx.x * 256 + threadIdx.x;   // slot column, 1024 total
    float ss = 0.f;
    for (int d = 0; d < DD; d++) { float v = phi[(size_t)d * SS + c]; ss += v * v; }
    float inv = scale[0] / fmaxf(sqrtf(ss), 1e-12f);
    for (int d = 0; d < DD; d++) g_phin[(size_t)d * SS + c] = phi[(size_t)d * SS + c] * inv;
}

// ---------------- segment partial sums (deterministic, no atomics) ----------------
// grid (32 token-groups, 6 dim-groups), 128 threads. mode0: sum xn; mode1: sum |xn-mean|
__global__ void k_seg(const int* __restrict__ ca, int mode) {
    __shared__ float acc[32][129];
    __shared__ float meanS[32][128];
    __shared__ float cnt[32];
    int tid = threadIdx.x;
    int tg = blockIdx.x, d0 = blockIdx.y * 128;
    for (int c = 0; c < 32; c++) {
        acc[c][tid] = 0.f;
        if (mode == 1) meanS[c][tid] = g_mean[c * DD + d0 + tid];
    }
    if (tid < 32) cnt[tid] = 0.f;
    __syncthreads();
    int t0 = tg * 256;
    for (int tt = 0; tt < 256; tt++) {
        int t = t0 + tt;
        int c = ca[(size_t)t * KK];
        float v = g_xn[(size_t)t * DD + d0 + tid];
        if (mode == 1) v = fabsf(v - meanS[c][tid]);
        acc[c][tid] += v;
        if (mode == 0 && blockIdx.y == 0 && tid == 0) cnt[c] += 1.f;
    }
    __syncthreads();
    for (int c = 0; c < 32; c++)
        g_part[((size_t)tg * 32 + c) * DD + d0 + tid] = acc[c][tid];
    if (mode == 0 && blockIdx.y == 0 && tid < 32) g_cpart[tg * 32 + tid] = cnt[tid];
}

// fixed-order reduction of partials -> mean (mode0) or w_mad (mode1)
__global__ void k_red(int mode) {
    int i = blockIdx.x * 256 + threadIdx.x;       // over 32*768
    if (i >= NE * DD) return;
    int c = i / DD, d = i % DD;
    float s = 0.f;
    for (int tg = 0; tg < 32; tg++) s += g_part[((size_t)tg * 32 + c) * DD + d];
    float cn = 0.f;
    for (int tg = 0; tg < 32; tg++) cn += g_cpart[tg * 32 + c];
    float m = (cn > 0.f) ? s / cn : 0.f;
    if (mode == 0) { g_mean[i] = m; if (d == 0) g_cnt[c] = cn; }
    else            g_mad[i] = m;
}

// ---------------- ACMoE W: clamp + renormalize ----------------
__global__ void k_W() {
    __shared__ float red[1024];
    int tid = threadIdx.x;
    float l = 0.f;
    for (int i = tid; i < NE * DD; i += 1024) l += 1.0f / (g_mad[i] + 0.35f);
    red[tid] = l; __syncthreads();
    for (int o = 512; o; o >>= 1) { if (tid < o) red[tid] += red[tid+o]; __syncthreads(); }
    float top = 5.0f * red[0] / (float)(NE * DD);
    __syncthreads();
    float l2 = 0.f;
    for (int i = tid; i < NE * DD; i += 1024) l2 += fminf(1.0f / (g_mad[i] + 0.35f), top);
    red[tid] = l2; __syncthreads();
    for (int o = 512; o; o >>= 1) { if (tid < o) red[tid] += red[tid+o]; __syncthreads(); }
    float m2 = red[0] / (float)(NE * DD);
    __syncthreads();
    for (int i = tid; i < NE * DD; i += 1024)
        g_W[i] = fminf(1.0f / (g_mad[i] + 0.35f), top) / m2;
}

__global__ void k_apply(const int* __restrict__ ca) {
    int t = blockIdx.x, tid = threadIdx.x;
    int c = ca[(size_t)t * KK];
    const float* Wr = g_W + (size_t)c * DD;
    float* xr = g_xn + (size_t)t * DD;
    xr[tid]       *= Wr[tid];
    xr[tid + 256] *= Wr[tid + 256];
    xr[tid + 512] *= Wr[tid + 512];
}

// ---------------- generic 128x128x8 SGEMM ----------------
// MODE0: logits = xw[8192,768] @ phin[768,1024]
// MODE1: xs (per batch z): disp^T[1024s,1024m] @ xw_b[1024,768] -> g_xs[n][b*32+p][d]
// MODE2: h (per expert z):  xs[256,768] @ w1[768,2048] +b1, gelu
// MODE3: ys (per expert z): h[256,2048] @ w2[2048,768] +b2
// MODE4: y (per batch z):   comb[1024,1024] @ ys(gathered)[1024,768] -> d_out
template<int MODE>
__global__ void __launch_bounds__(256, 2) gemm_k(const float* __restrict__ Bext,
                                                 const float* __restrict__ biasext,
                                                 float* __restrict__ Cext) {
    constexpr int KD = (MODE==0)?768 : (MODE==1)?1024 : (MODE==2)?768 : (MODE==3)?2048 : 1024;
    const int z = blockIdx.z;
    const int i0 = blockIdx.y * 128, j0 = blockIdx.x * 128;
    const int tid = threadIdx.x;
    __shared__ float As[8][132];
    __shared__ float Bs[8][128];

    const float* Aptr = nullptr; int lda = 0;
    const float* Bptr = nullptr; int ldb = 0;
    if constexpr (MODE==0) { Aptr = g_xn;  lda = 768;  Bptr = g_phin; ldb = 1024; }
    if constexpr (MODE==1) { Aptr = g_disp + (size_t)z*1024*1024;
                             Bptr = g_xn  + (size_t)z*1024*768; ldb = 768; }
    if constexpr (MODE==2) { Aptr = g_xs + (size_t)z*256*768;  lda = 768;
                             Bptr = Bext + (size_t)z*768*2048; ldb = 2048; }
    if constexpr (MODE==3) { Aptr = g_h  + (size_t)z*256*2048; lda = 2048;
                             Bptr = Bext + (size_t)z*2048*768; ldb = 768; }
    if constexpr (MODE==4) { Aptr = g_logits + (size_t)z*1024*1024; lda = 1024; Bptr = g_ys; }

    float acc[8][8];
    #pragma unroll
    for (int u = 0; u < 8; u++)
        #pragma unroll
        for (int w = 0; w < 8; w++) acc[u][w] = 0.f;

    const int tr = tid >> 4, tc = tid & 15;

    for (int k0 = 0; k0 < KD; k0 += 8) {
        if constexpr (MODE == 1) {
            int k = tid >> 5, j4 = (tid & 31) * 4;
            float4 va = *(const float4*)(Aptr + (size_t)(k0 + k) * 1024 + i0 + j4);
            *(float4*)&As[k][j4] = va;
        } else {
            int i = tid >> 1, kp = (tid & 1) * 4;
            float4 va = *(const float4*)(Aptr + (size_t)(i0 + i) * lda + k0 + kp);
            As[kp+0][i] = va.x; As[kp+1][i] = va.y; As[kp+2][i] = va.z; As[kp+3][i] = va.w;
        }
        {
            int k = tid >> 5, j = (tid & 31) * 4;
            const float* src;
            if constexpr (MODE == 4) {
                int s = k0 + k;
                src = Bptr + (size_t)((s >> 5) * 256 + z * 32 + (s & 31)) * 768 + j0 + j;
            } else {
                src = Bptr + (size_t)(k0 + k) * ldb + j0 + j;
            }
            *(float4*)&Bs[k][j] = *(const float4*)src;
        }
        __syncthreads();
        #pragma unroll
        for (int kk = 0; kk < 8; kk++) {
            float a[8], b[8];
            *(float4*)&a[0] = *(const float4*)&As[kk][tr*8];
            *(float4*)&a[4] = *(const float4*)&As[kk][tr*8+4];
            *(float4*)&b[0] = *(const float4*)&Bs[kk][tc*8];
            *(float4*)&b[4] = *(const float4*)&Bs[kk][tc*8+4];
            #pragma unroll
            for (int u = 0; u < 8; u++)
                #pragma unroll
                for (int w = 0; w < 8; w++) acc[u][w] = fmaf(a[u], b[w], acc[u][w]);
        }
        __syncthreads();
    }

    float bcol[8];
    if constexpr (MODE==2 || MODE==3) {
        const float* bptr = biasext + (size_t)z * ((MODE==2)?2048:768) + j0 + tc*8;
        *(float4*)&bcol[0] = *(const float4*)bptr;
        *(float4*)&bcol[4] = *(const float4*)(bptr + 4);
    }
    #pragma unroll
    for (int u = 0; u < 8; u++) {
        int row = i0 + tr*8 + u;
        float* crow;
        if constexpr (MODE==0) crow = g_logits + (size_t)row * 1024 + j0;
        if constexpr (MODE==1) crow = g_xs + (size_t)((row >> 5) * 256 + z * 32 + (row & 31)) * 768 + j0;
        if constexpr (MODE==2) crow = g_h  + (size_t)z*256*2048 + (size_t)row * 2048 + j0;
        if constexpr (MODE==3) crow = g_ys + (size_t)z*256*768  + (size_t)row * 768  + j0;
        if constexpr (MODE==4) crow = Cext + (size_t)z*1024*768 + (size_t)row * 768  + j0;
        float o[8];
        #pragma unroll
        for (int w = 0; w < 8; w++) {
            float val = acc[u][w];
            if constexpr (MODE==2) val = gelu_f(val + bcol[w]);
            if constexpr (MODE==3) val += bcol[w];
            o[w] = val;
        }
        *(float4*)(crow + tc*8)     = *(float4*)&o[0];
        *(float4*)(crow + tc*8 + 4) = *(float4*)&o[4];
    }
}

// ---------------- top-k (K=8) per token, jax tie-break semantics ----------------
__global__ void k_topk(float* __restrict__ mix, float* __restrict__ clus) {
    int warp = threadIdx.x >> 5, lane = threadIdx.x & 31;
    int row = blockIdx.x * 8 + warp;
    const float* L = g_logits + (size_t)row * SS;
    float v[32];
    #pragma unroll
    for (int j = 0; j < 32; j++) v[j] = L[j * 32 + lane];
    float lastv = INFINITY; int lasti = -1;
    #pragma unroll
    for (int sel = 0; sel < 8; sel++) {
        float bv = -INFINITY; int bi = 1 << 30;
        #pragma unroll
        for (int j = 0; j < 32; j++) {
            int gi = j * 32 + lane;
            float val = v[j];
            bool elig   = (val < lastv) || ((val == lastv) && (gi > lasti));
            bool better = (val > bv)    || ((val == bv)    && (gi < bi));
            if (elig && better) { bv = val; bi = gi; }
        }
        for (int o = 16; o; o >>= 1) {
            float ov = __shfl_xor_sync(0xffffffff, bv, o);
            int   oi = __shfl_xor_sync(0xffffffff, bi, o);
            if ((ov > bv) || ((ov == bv) && (oi < bi))) { bv = ov; bi = oi; }
        }
        lastv = bv; lasti = bi;
        if (lane == 0) {
            mix [(size_t)row * 8 + sel] = bv;
            clus[(size_t)row * 8 + sel] = (float)(bi >> 5);   // P = 32
        }
    }
}

// ---------------- softmax statistics ----------------
__global__ void k_rowstats() {   // comb: softmax over slots per token
    int t = blockIdx.x, tid = threadIdx.x;
    const float4* row = (const float4*)(g_logits + (size_t)t * SS);
    float4 v = row[tid];
    __shared__ float red[256];
    red[tid] = fmaxf(fmaxf(v.x, v.y), fmaxf(v.z, v.w));
    __syncthreads();
    for (int o = 128; o; o >>= 1) { if (tid < o) red[tid] = fmaxf(red[tid], red[tid+o]); __syncthreads(); }
    float rm = red[0];
    __syncthreads();
    red[tid] = expf(v.x - rm) + expf(v.y - rm) + expf(v.z - rm) + expf(v.w - rm);
    __syncthreads();
    for (int o = 128; o; o >>= 1) { if (tid < o) red[tid] += red[tid+o]; __syncthreads(); }
    if (tid == 0) { g_rowmax[t] = rm; g_rowsum[t] = red[0]; }
}

__global__ void k_colstats() {   // disp: softmax over tokens per (b, slot)
    int b = blockIdx.y, s0 = blockIdx.x * 32;
    int sl = threadIdx.x & 31, mr = threadIdx.x >> 5;   // 8 row-lanes x 32 slots
    const float* base = g_logits + (size_t)b * MM * SS + s0 + sl;
    float mx = -INFINITY;
    for (int m = mr; m < MM; m += 8) mx = fmaxf(mx, base[(size_t)m * SS]);
    __shared__ float pm[8][33], ps[8][33];
    pm[mr][sl] = mx; __syncthreads();
    if (mr == 0) { float v = pm[0][sl]; for (int r = 1; r < 8; r++) v = fmaxf(v, pm[r][sl]); pm[0][sl] = v; }
    __syncthreads();
    float cm = pm[0][sl];
    float sm = 0.f;
    for (int m = mr; m < MM; m += 8) sm += expf(base[(size_t)m * SS] - cm);
    ps[mr][sl] = sm; __syncthreads();
    if (mr == 0) {
        float v = 0.f; for (int r = 0; r < 8; r++) v += ps[r][sl];
        g_colmax[b * SS + s0 + sl] = cm;
        g_colsum[b * SS + s0 + sl] = v;
    }
}

__global__ void k_dispcomb() {   // write disp; overwrite logits with comb
    int t = blockIdx.x, tid = threadIdx.x;
    int b = t >> 10;
    int j = tid * 4;
    float4 l  = *(float4*)(g_logits + (size_t)t * SS + j);
    float4 cm = *(float4*)(g_colmax + (size_t)b * SS + j);
    float4 cs = *(float4*)(g_colsum + (size_t)b * SS + j);
    float rm = g_rowmax[t], rs = g_rowsum[t];
    float4 dsp = { expf(l.x - cm.x)/cs.x, expf(l.y - cm.y)/cs.y,
                   expf(l.z - cm.z)/cs.z, expf(l.w - cm.w)/cs.w };
    float4 cb  = { expf(l.x - rm)/rs, expf(l.y - rm)/rs,
                   expf(l.z - rm)/rs, expf(l.w - rm)/rs };
    *(float4*)(g_disp   + (size_t)t * SS + j) = dsp;
    *(float4*)(g_logits + (size_t)t * SS + j) = cb;
}

// ---------------- launch ----------------
extern "C" void kernel_launch(void* const* d_in, const int* in_sizes, int n_in,
                              void* d_out, int out_size) {
    const float* x     = (const float*)d_in[0];
    const int*   ca    = (const int*)  d_in[1];
    const float* phi   = (const float*)d_in[2];
    const float* scale = (const float*)d_in[3];
    const float* w1    = (const float*)d_in[4];
    const float* b1    = (const float*)d_in[5];
    const float* w2    = (const float*)d_in[6];
    const float* b2    = (const float*)d_in[7];
    float* out = (float*)d_out;

    const int Y_ELEMS = BB * MM * DD;          // 6291456
    float* mixo = nullptr; float* cluso = nullptr;
    if (out_size >= Y_ELEMS + 2 * TT * KK) {   // tuple (y, mixing_weights, new_clusters)
        mixo  = out + Y_ELEMS;
        cluso = mixo + TT * KK;
    }

    k_norm_x<<<TT, 256>>>(x);
    k_norm_phi<<<4, 256>>>(phi, scale);
    k_seg<<<dim3(32, 6), 128>>>(ca, 0);
    k_red<<<96, 256>>>(0);
    k_seg<<<dim3(32, 6), 128>>>(ca, 1);
    k_red<<<96, 256>>>(1);
    k_W<<<1, 1024>>>();
    k_apply<<<TT, 256>>>(ca);

    gemm_k<0><<<dim3(8, 64, 1), 256>>>(nullptr, nullptr, nullptr);   // logits

    if (mixo) k_topk<<<1024, 256>>>(mixo, cluso);
    k_rowstats<<<TT, 256>>>();
    k_colstats<<<dim3(32, BB), 256>>>();
    k_dispcomb<<<TT, 256>>>();

    gemm_k<1><<<dim3(6, 8, BB), 256>>>(nullptr, nullptr, nullptr);   // xs
    gemm_k<2><<<dim3(16, 2, NE), 256>>>(w1, b1, nullptr);            // h = gelu(xs@w1+b1)
    gemm_k<3><<<dim3(6, 2, NE), 256>>>(w2, b2, nullptr);             // ys = h@w2+b2
    gemm_k<4><<<dim3(6, 8, BB), 256>>>(nullptr, nullptr, out);       // y
}

// round 3
// speedup vs baseline: 2.2042x; 2.2042x over previous
#include <cuda_runtime.h>
#include <math.h>
#include <stdint.h>

// ---------------- problem constants ----------------
#define BB   8
#define MM   1024
#define DD   768
#define NE   32
#define PE   32
#define KK   8
#define HH   2048
#define SS   1024            // N*P
#define TT   8192            // B*M

// ---------------- scratch (device globals; no allocs allowed) ----------------
__device__ float g_xn   [TT * DD];          // xn, then xw in-place
__device__ float g_phin [DD * SS];
__device__ float g_part [32 * NE * DD];
__device__ float g_cpart[32 * NE];
__device__ float g_mean [NE * DD];
__device__ float g_mad  [NE * DD];
__device__ float g_W    [NE * DD];
__device__ float g_cnt  [NE];
__device__ float g_logits[TT * SS];         // logits, later overwritten by comb
__device__ float g_disp [TT * SS];
__device__ float g_rowmax[TT], g_rowsum[TT];
__device__ float g_colmax[BB * SS], g_colsum[BB * SS];
__device__ float g_xs [NE * (BB*PE) * DD];  // [n][b*32+p][d]
__device__ float g_h  [NE * (BB*PE) * HH];
__device__ float g_ys [NE * (BB*PE) * DD];

__device__ __forceinline__ float gelu_f(float v) {
    return 0.5f * v * (1.0f + erff(v * 0.70710678118654752440f));
}

__device__ __forceinline__ float tf32r(float x) {
    uint32_t r;
    asm("cvt.rna.tf32.f32 %0, %1;" : "=r"(r) : "f"(x));
    return __uint_as_float(r);
}

__device__ __forceinline__ void mma_tf32(float* c, const uint32_t* a,
                                         uint32_t b0, uint32_t b1) {
    asm volatile(
        "mma.sync.aligned.m16n8k8.row.col.f32.tf32.tf32.f32 "
        "{%0,%1,%2,%3}, {%4,%5,%6,%7}, {%8,%9}, {%0,%1,%2,%3};"
        : "+f"(c[0]), "+f"(c[1]), "+f"(c[2]), "+f"(c[3])
        : "r"(a[0]), "r"(a[1]), "r"(a[2]), "r"(a[3]), "r"(b0), "r"(b1));
}

// ---------------- token L2 normalize ----------------
__global__ void k_norm_x(const float* __restrict__ x) {
    int t = blockIdx.x, tid = threadIdx.x;
    const float* xr = x + (size_t)t * DD;
    float v0 = xr[tid], v1 = xr[tid + 256], v2 = xr[tid + 512];
    __shared__ float red[256];
    red[tid] = v0*v0 + v1*v1 + v2*v2;
    __syncthreads();
    for (int o = 128; o; o >>= 1) { if (tid < o) red[tid] += red[tid+o]; __syncthreads(); }
    float inv = 1.0f / fmaxf(sqrtf(red[0]), 1e-12f);
    float* o = g_xn + (size_t)t * DD;
    o[tid] = v0*inv; o[tid+256] = v1*inv; o[tid+512] = v2*inv;
}

// ---------------- phi column normalize + scale ----------------
__global__ void k_norm_phi(const float* __restrict__ phi, const float* __restrict__ scale) {
    int c = blockIdx.x * 256 + threadIdx.x;
    float ss = 0.f;
    for (int d = 0; d < DD; d++) { float v = phi[(size_t)d * SS + c]; ss += v * v; }
    float inv = scale[0] / fmaxf(sqrtf(ss), 1e-12f);
    for (int d = 0; d < DD; d++) g_phin[(size_t)d * SS + c] = phi[(size_t)d * SS + c] * inv;
}

// ---------------- segment partial sums (deterministic, no atomics) ----------------
__global__ void k_seg(const int* __restrict__ ca, int mode) {
    __shared__ float acc[32][129];
    __shared__ float meanS[32][128];
    __shared__ float cnt[32];
    int tid = threadIdx.x;
    int tg = blockIdx.x, d0 = blockIdx.y * 128;
    for (int c = 0; c < 32; c++) {
        acc[c][tid] = 0.f;
        if (mode == 1) meanS[c][tid] = g_mean[c * DD + d0 + tid];
    }
    if (tid < 32) cnt[tid] = 0.f;
    __syncthreads();
    int t0 = tg * 256;
    for (int tt = 0; tt < 256; tt++) {
        int t = t0 + tt;
        int c = ca[(size_t)t * KK];
        float v = g_xn[(size_t)t * DD + d0 + tid];
        if (mode == 1) v = fabsf(v - meanS[c][tid]);
        acc[c][tid] += v;
        if (mode == 0 && blockIdx.y == 0 && tid == 0) cnt[c] += 1.f;
    }
    __syncthreads();
    for (int c = 0; c < 32; c++)
        g_part[((size_t)tg * 32 + c) * DD + d0 + tid] = acc[c][tid];
    if (mode == 0 && blockIdx.y == 0 && tid < 32) g_cpart[tg * 32 + tid] = cnt[tid];
}

__global__ void k_red(int mode) {
    int i = blockIdx.x * 256 + threadIdx.x;
    if (i >= NE * DD) return;
    int c = i / DD, d = i % DD;
    float s = 0.f;
    for (int tg = 0; tg < 32; tg++) s += g_part[((size_t)tg * 32 + c) * DD + d];
    float cn = 0.f;
    for (int tg = 0; tg < 32; tg++) cn += g_cpart[tg * 32 + c];
    float m = (cn > 0.f) ? s / cn : 0.f;
    if (mode == 0) { g_mean[i] = m; if (d == 0) g_cnt[c] = cn; }
    else            g_mad[i] = m;
}

// ---------------- ACMoE W: clamp + renormalize ----------------
__global__ void k_W() {
    __shared__ float red[1024];
    int tid = threadIdx.x;
    float l = 0.f;
    for (int i = tid; i < NE * DD; i += 1024) l += 1.0f / (g_mad[i] + 0.35f);
    red[tid] = l; __syncthreads();
    for (int o = 512; o; o >>= 1) { if (tid < o) red[tid] += red[tid+o]; __syncthreads(); }
    float top = 5.0f * red[0] / (float)(NE * DD);
    __syncthreads();
    float l2 = 0.f;
    for (int i = tid; i < NE * DD; i += 1024) l2 += fminf(1.0f / (g_mad[i] + 0.35f), top);
    red[tid] = l2; __syncthreads();
    for (int o = 512; o; o >>= 1) { if (tid < o) red[tid] += red[tid+o]; __syncthreads(); }
    float m2 = red[0] / (float)(NE * DD);
    __syncthreads();
    for (int i = tid; i < NE * DD; i += 1024)
        g_W[i] = fminf(1.0f / (g_mad[i] + 0.35f), top) / m2;
}

__global__ void k_apply(const int* __restrict__ ca) {
    int t = blockIdx.x, tid = threadIdx.x;
    int c = ca[(size_t)t * KK];
    const float* Wr = g_W + (size_t)c * DD;
    float* xr = g_xn + (size_t)t * DD;
    xr[tid]       *= Wr[tid];
    xr[tid + 256] *= Wr[tid + 256];
    xr[tid + 512] *= Wr[tid + 512];
}

// ---------------- exact fp32 SGEMM (logits only; protects top-k ordering) ----------------
template<int MODE>
__global__ void __launch_bounds__(256, 2) gemm_k(const float* __restrict__ Bext,
                                                 const float* __restrict__ biasext,
                                                 float* __restrict__ Cext) {
    constexpr int KD = 768;
    const int i0 = blockIdx.y * 128, j0 = blockIdx.x * 128;
    const int tid = threadIdx.x;
    __shared__ float As[8][132];
    __shared__ float Bs[8][128];

    const float* Aptr = g_xn;  const int lda = 768;
    const float* Bptr = g_phin; const int ldb = 1024;

    float acc[8][8];
    #pragma unroll
    for (int u = 0; u < 8; u++)
        #pragma unroll
        for (int w = 0; w < 8; w++) acc[u][w] = 0.f;

    const int tr = tid >> 4, tc = tid & 15;

    for (int k0 = 0; k0 < KD; k0 += 8) {
        {
            int i = tid >> 1, kp = (tid & 1) * 4;
            float4 va = *(const float4*)(Aptr + (size_t)(i0 + i) * lda + k0 + kp);
            As[kp+0][i] = va.x; As[kp+1][i] = va.y; As[kp+2][i] = va.z; As[kp+3][i] = va.w;
        }
        {
            int k = tid >> 5, j = (tid & 31) * 4;
            *(float4*)&Bs[k][j] = *(const float4*)(Bptr + (size_t)(k0 + k) * ldb + j0 + j);
        }
        __syncthreads();
        #pragma unroll
        for (int kk = 0; kk < 8; kk++) {
            float a[8], b[8];
            *(float4*)&a[0] = *(const float4*)&As[kk][tr*8];
            *(float4*)&a[4] = *(const float4*)&As[kk][tr*8+4];
            *(float4*)&b[0] = *(const float4*)&Bs[kk][tc*8];
            *(float4*)&b[4] = *(const float4*)&Bs[kk][tc*8+4];
            #pragma unroll
            for (int u = 0; u < 8; u++)
                #pragma unroll
                for (int w = 0; w < 8; w++) acc[u][w] = fmaf(a[u], b[w], acc[u][w]);
        }
        __syncthreads();
    }

    #pragma unroll
    for (int u = 0; u < 8; u++) {
        int row = i0 + tr*8 + u;
        float* crow = g_logits + (size_t)row * 1024 + j0;
        *(float4*)(crow + tc*8)     = *(float4*)&acc[u][0];
        *(float4*)(crow + tc*8 + 4) = *(float4*)&acc[u][4];
    }
}

// ---------------- tf32 tensor-core GEMM (modes 1..4) ----------------
// Block tile 128x128, BK=16, 8 warps in 4(m)x2(n), warp tile 32x64,
// mma.sync m16n8k8 tf32, double-buffered smem, fp32 accumulate.
// MODE1: xs = disp^T[1024s,1024m] @ xn_b[1024m,768]  (A k-major), scatter-out
// MODE2: h  = gelu(xs[256,768] @ w1[768,2048] + b1)
// MODE3: ys = h[256,2048] @ w2[2048,768] + b2
// MODE4: y  = comb[1024,1024] @ ys_gathered[1024,768]
template<int MODE>
__global__ void __launch_bounds__(256, 2) gemm_tc(const float* __restrict__ Bext,
                                                   const float* __restrict__ biasext,
                                                   float* __restrict__ Cext) {
    constexpr int KD = (MODE==1)?1024 : (MODE==2)?768 : (MODE==3)?2048 : 1024;
    constexpr int BK = 16;
    constexpr bool AKMAJ = (MODE==1);
    const int z = blockIdx.z;
    const int i0 = blockIdx.y * 128, j0 = blockIdx.x * 128;
    const int tid = threadIdx.x, lane = tid & 31, warp = tid >> 5;
    const int wm = warp & 3, wn = warp >> 1 & 0;  // placeholder (fixed below)
    const int wmi = warp & 3;          // 0..3  (m)
    const int wni = warp >> 2;         // 0..1  (n)

    __shared__ float As[2][BK][136];
    __shared__ float Bs[2][BK][136];

    const float* Aptr = nullptr; int lda = 0;
    const float* Bptr = nullptr; int ldb = 0;
    if constexpr (MODE==1) { Aptr = g_disp + (size_t)z*1024*1024;
                             Bptr = g_xn  + (size_t)z*1024*768; ldb = 768; }
    if constexpr (MODE==2) { Aptr = g_xs + (size_t)z*256*768;   lda = 768;
                             Bptr = Bext + (size_t)z*768*2048;  ldb = 2048; }
    if constexpr (MODE==3) { Aptr = g_h  + (size_t)z*256*2048;  lda = 2048;
                             Bptr = Bext + (size_t)z*2048*768;  ldb = 768; }
    if constexpr (MODE==4) { Aptr = g_logits + (size_t)z*1024*1024; lda = 1024;
                             Bptr = g_ys; ldb = 768; }
    (void)wm; (void)wn;

    // staging indices
    const int akk = tid >> 4, ac = (tid & 15) * 8;      // k-major A / all B
    const int ar  = tid >> 1, akq = (tid & 1) * 8;      // row-major A

    float acc[2][8][4];
    #pragma unroll
    for (int mf = 0; mf < 2; mf++)
        #pragma unroll
        for (int nf = 0; nf < 8; nf++)
            #pragma unroll
            for (int q = 0; q < 4; q++) acc[mf][nf][q] = 0.f;

    float4 ra0, ra1, rb0, rb1;

    auto loadg = [&](int k0) {
        if constexpr (AKMAJ) {
            const float* p = Aptr + (size_t)(k0 + akk) * 1024 + i0 + ac;
            ra0 = *(const float4*)p; ra1 = *(const float4*)(p + 4);
        } else {
            const float* p = Aptr + (size_t)(i0 + ar) * lda + k0 + akq;
            ra0 = *(const float4*)p; ra1 = *(const float4*)(p + 4);
        }
        if constexpr (MODE==4) {
            int s = k0 + akk;
            const float* p = Bptr + (size_t)((s >> 5) * 256 + z * 32 + (s & 31)) * 768 + j0 + ac;
            rb0 = *(const float4*)p; rb1 = *(const float4*)(p + 4);
        } else {
            const float* p = Bptr + (size_t)(k0 + akk) * ldb + j0 + ac;
            rb0 = *(const float4*)p; rb1 = *(const float4*)(p + 4);
        }
    };

    auto stage = [&](int buf) {
        if constexpr (AKMAJ) {
            float* d = &As[buf][akk][ac];
            d[0]=tf32r(ra0.x); d[1]=tf32r(ra0.y); d[2]=tf32r(ra0.z); d[3]=tf32r(ra0.w);
            d[4]=tf32r(ra1.x); d[5]=tf32r(ra1.y); d[6]=tf32r(ra1.z); d[7]=tf32r(ra1.w);
        } else {
            As[buf][akq+0][ar]=tf32r(ra0.x); As[buf][akq+1][ar]=tf32r(ra0.y);
            As[buf][akq+2][ar]=tf32r(ra0.z); As[buf][akq+3][ar]=tf32r(ra0.w);
            As[buf][akq+4][ar]=tf32r(ra1.x); As[buf][akq+5][ar]=tf32r(ra1.y);
            As[buf][akq+6][ar]=tf32r(ra1.z); As[buf][akq+7][ar]=tf32r(ra1.w);
        }
        float* d = &Bs[buf][akk][ac];
        d[0]=tf32r(rb0.x); d[1]=tf32r(rb0.y); d[2]=tf32r(rb0.z); d[3]=tf32r(rb0.w);
        d[4]=tf32r(rb1.x); d[5]=tf32r(rb1.y); d[6]=tf32r(rb1.z); d[7]=tf32r(rb1.w);
    };

    auto compute = [&](int buf) {
        #pragma unroll
        for (int ks = 0; ks < 2; ks++) {
            const int kb = ks * 8 + (lane & 3);
            const int rbase = wmi * 32 + (lane >> 2);
            uint32_t af[2][4];
            #pragma unroll
            for (int mf = 0; mf < 2; mf++) {
                af[mf][0] = __float_as_uint(As[buf][kb  ][rbase + mf*16]);
                af[mf][1] = __float_as_uint(As[buf][kb  ][rbase + mf*16 + 8]);
                af[mf][2] = __float_as_uint(As[buf][kb+4][rbase + mf*16]);
                af[mf][3] = __float_as_uint(As[buf][kb+4][rbase + mf*16 + 8]);
            }
            #pragma unroll
            for (int nf = 0; nf < 8; nf++) {
                const int nidx = wni * 64 + nf * 8 + (lane >> 2);
                uint32_t bf0 = __float_as_uint(Bs[buf][kb  ][nidx]);
                uint32_t bf1 = __float_as_uint(Bs[buf][kb+4][nidx]);
                mma_tf32(acc[0][nf], af[0], bf0, bf1);
                mma_tf32(acc[1][nf], af[1], bf0, bf1);
            }
        }
    };

    loadg(0);
    stage(0);
    __syncthreads();

    for (int k0 = 0, it = 0; k0 < KD; k0 += BK, it++) {
        const int buf = it & 1;
        const bool more = (k0 + BK) < KD;
        if (more) loadg(k0 + BK);
        compute(buf);
        if (more) stage(buf ^ 1);
        __syncthreads();
    }

    // epilogue
    #pragma unroll
    for (int mf = 0; mf < 2; mf++) {
        const int r0 = i0 + wmi * 32 + mf * 16 + (lane >> 2);
        #pragma unroll
        for (int nf = 0; nf < 8; nf++) {
            const int c = j0 + wni * 64 + nf * 8 + (lane & 3) * 2;
            float v00 = acc[mf][nf][0], v01 = acc[mf][nf][1];
            float v10 = acc[mf][nf][2], v11 = acc[mf][nf][3];
            if constexpr (MODE==2) {
                const float* bp = biasext + (size_t)z * 2048 + c;
                float bx = bp[0], by = bp[1];
                v00 = gelu_f(v00 + bx); v01 = gelu_f(v01 + by);
                v10 = gelu_f(v10 + bx); v11 = gelu_f(v11 + by);
            }
            if constexpr (MODE==3) {
                const float* bp = biasext + (size_t)z * 768 + c;
                float bx = bp[0], by = bp[1];
                v00 += bx; v01 += by; v10 += bx; v11 += by;
            }
            float* o0; float* o1;
            if constexpr (MODE==1) {
                int rr0 = r0, rr1 = r0 + 8;
                o0 = g_xs + (size_t)((rr0 >> 5) * 256 + z * 32 + (rr0 & 31)) * 768 + c;
                o1 = g_xs + (size_t)((rr1 >> 5) * 256 + z * 32 + (rr1 & 31)) * 768 + c;
            }
            if constexpr (MODE==2) {
                o0 = g_h + (size_t)z*256*2048 + (size_t)r0 * 2048 + c;
                o1 = o0 + (size_t)8 * 2048;
            }
            if constexpr (MODE==3) {
                o0 = g_ys + (size_t)z*256*768 + (size_t)r0 * 768 + c;
                o1 = o0 + (size_t)8 * 768;
            }
            if constexpr (MODE==4) {
                o0 = Cext + (size_t)z*1024*768 + (size_t)r0 * 768 + c;
                o1 = o0 + (size_t)8 * 768;
            }
            float2 w0 = {v00, v01}, w1 = {v10, v11};
            *(float2*)o0 = w0;
            *(float2*)o1 = w1;
        }
    }
}

// ---------------- top-k (K=8) per token, jax tie-break semantics ----------------
__global__ void k_topk(float* __restrict__ mix, float* __restrict__ clus) {
    int warp = threadIdx.x >> 5, lane = threadIdx.x & 31;
    int row = blockIdx.x * 8 + warp;
    const float* L = g_logits + (size_t)row * SS;
    float v[32];
    #pragma unroll
    for (int j = 0; j < 32; j++) v[j] = L[j * 32 + lane];
    float lastv = INFINITY; int lasti = -1;
    #pragma unroll
    for (int sel = 0; sel < 8; sel++) {
        float bv = -INFINITY; int bi = 1 << 30;
        #pragma unroll
        for (int j = 0; j < 32; j++) {
            int gi = j * 32 + lane;
            float val = v[j];
            bool elig   = (val < lastv) || ((val == lastv) && (gi > lasti));
            bool better = (val > bv)    || ((val == bv)    && (gi < bi));
            if (elig && better) { bv = val; bi = gi; }
        }
        for (int o = 16; o; o >>= 1) {
            float ov = __shfl_xor_sync(0xffffffff, bv, o);
            int   oi = __shfl_xor_sync(0xffffffff, bi, o);
            if ((ov > bv) || ((ov == bv) && (oi < bi))) { bv = ov; bi = oi; }
        }
        lastv = bv; lasti = bi;
        if (lane == 0) {
            mix [(size_t)row * 8 + sel] = bv;
            clus[(size_t)row * 8 + sel] = (float)(bi >> 5);
        }
    }
}

// ---------------- softmax statistics ----------------
__global__ void k_rowstats() {
    int t = blockIdx.x, tid = threadIdx.x;
    const float4* row = (const float4*)(g_logits + (size_t)t * SS);
    float4 v = row[tid];
    __shared__ float red[256];
    red[tid] = fmaxf(fmaxf(v.x, v.y), fmaxf(v.z, v.w));
    __syncthreads();
    for (int o = 128; o; o >>= 1) { if (tid < o) red[tid] = fmaxf(red[tid], red[tid+o]); __syncthreads(); }
    float rm = red[0];
    __syncthreads();
    red[tid] = expf(v.x - rm) + expf(v.y - rm) + expf(v.z - rm) + expf(v.w - rm);
    __syncthreads();
    for (int o = 128; o; o >>= 1) { if (tid < o) red[tid] += red[tid+o]; __syncthreads(); }
    if (tid == 0) { g_rowmax[t] = rm; g_rowsum[t] = red[0]; }
}

__global__ void k_colstats() {
    int b = blockIdx.y, s0 = blockIdx.x * 32;
    int sl = threadIdx.x & 31, mr = threadIdx.x >> 5;
    const float* base = g_logits + (size_t)b * MM * SS + s0 + sl;
    float mx = -INFINITY;
    for (int m = mr; m < MM; m += 8) mx = fmaxf(mx, base[(size_t)m * SS]);
    __shared__ float pm[8][33], ps[8][33];
    pm[mr][sl] = mx; __syncthreads();
    if (mr == 0) { float v = pm[0][sl]; for (int r = 1; r < 8; r++) v = fmaxf(v, pm[r][sl]); pm[0][sl] = v; }
    __syncthreads();
    float cm = pm[0][sl];
    float sm = 0.f;
    for (int m = mr; m < MM; m += 8) sm += expf(base[(size_t)m * SS] - cm);
    ps[mr][sl] = sm; __syncthreads();
    if (mr == 0) {
        float v = 0.f; for (int r = 0; r < 8; r++) v += ps[r][sl];
        g_colmax[b * SS + s0 + sl] = cm;
        g_colsum[b * SS + s0 + sl] = v;
    }
}

__global__ void k_dispcomb() {
    int t = blockIdx.x, tid = threadIdx.x;
    int b = t >> 10;
    int j = tid * 4;
    float4 l  = *(float4*)(g_logits + (size_t)t * SS + j);
    float4 cm = *(float4*)(g_colmax + (size_t)b * SS + j);
    float4 cs = *(float4*)(g_colsum + (size_t)b * SS + j);
    float rm = g_rowmax[t], rs = g_rowsum[t];
    float4 dsp = { expf(l.x - cm.x)/cs.x, expf(l.y - cm.y)/cs.y,
                   expf(l.z - cm.z)/cs.z, expf(l.w - cm.w)/cs.w };
    float4 cb  = { expf(l.x - rm)/rs, expf(l.y - rm)/rs,
                   expf(l.z - rm)/rs, expf(l.w - rm)/rs };
    *(float4*)(g_disp   + (size_t)t * SS + j) = dsp;
    *(float4*)(g_logits + (size_t)t * SS + j) = cb;
}

// ---------------- launch ----------------
extern "C" void kernel_launch(void* const* d_in, const int* in_sizes, int n_in,
                              void* d_out, int out_size) {
    const float* x     = (const float*)d_in[0];
    const int*   ca    = (const int*)  d_in[1];
    const float* phi   = (const float*)d_in[2];
    const float* scale = (const float*)d_in[3];
    const float* w1    = (const float*)d_in[4];
    const float* b1    = (const float*)d_in[5];
    const float* w2    = (const float*)d_in[6];
    const float* b2    = (const float*)d_in[7];
    float* out = (float*)d_out;

    const int Y_ELEMS = BB * MM * DD;
    float* mixo = nullptr; float* cluso = nullptr;
    if (out_size >= Y_ELEMS + 2 * TT * KK) {
        mixo  = out + Y_ELEMS;
        cluso = mixo + TT * KK;
    }

    k_norm_x<<<TT, 256>>>(x);
    k_norm_phi<<<4, 256>>>(phi, scale);
    k_seg<<<dim3(32, 6), 128>>>(ca, 0);
    k_red<<<96, 256>>>(0);
    k_seg<<<dim3(32, 6), 128>>>(ca, 1);
    k_red<<<96, 256>>>(1);
    k_W<<<1, 1024>>>();
    k_apply<<<TT, 256>>>(ca);

    gemm_k<0><<<dim3(8, 64, 1), 256>>>(nullptr, nullptr, nullptr);   // logits (exact fp32)

    if (mixo) k_topk<<<1024, 256>>>(mixo, cluso);
    k_rowstats<<<TT, 256>>>();
    k_colstats<<<dim3(32, BB), 256>>>();
    k_dispcomb<<<TT, 256>>>();

    gemm_tc<1><<<dim3(6, 8, BB), 256>>>(nullptr, nullptr, nullptr);  // xs      (tf32 TC)
    gemm_tc<2><<<dim3(16, 2, NE), 256>>>(w1, b1, nullptr);           // h       (tf32 TC)
    gemm_tc<3><<<dim3(6, 2, NE), 256>>>(w2, b2, nullptr);            // ys      (tf32 TC)
    gemm_tc<4><<<dim3(6, 8, BB), 256>>>(nullptr, nullptr, out);      // y       (tf32 TC)
}